// round 8
// baseline (speedup 1.0000x reference)
#include <cuda_runtime.h>
#include <cstdint>
#include <math.h>

#define B_TOTAL 65536
#define KDIM 512
#define W_TOTAL (512*512*5 + 128*512)

// Pre-split activation ping-pong buffers + weight hi/lo (allocation-free scratch).
__device__ float g_hiA[(size_t)B_TOTAL * KDIM];
__device__ float g_loA[(size_t)B_TOTAL * KDIM];
__device__ float g_hiB[(size_t)B_TOTAL * KDIM];
__device__ float g_loB[(size_t)B_TOTAL * KDIM];
__device__ float g_Wh[W_TOTAL];
__device__ float g_Wl[W_TOTAL];

__device__ __forceinline__ float act_clip(float h, int f, float mx) {
    float o;
    if (f == 0) {
        o = fmaxf(h, 0.0f);                       // ReLU
    } else if (f == 1) {
        o = 1.0f / (1.0f + __expf(-h));           // Sigmoid
    } else if (f == 2) {
        o = tanhf(h);                             // Tanh
    } else if (f == 3) {
        o = (h > 0.0f) ? h : 0.1f * h;            // LeakyReLU(0.1)
    } else {
        const float sc = 1.0507009873554805f;     // SELU
        const float al = 1.6732632423543772f;
        o = (h > 0.0f) ? sc * h : sc * al * (__expf(h) - 1.0f);
    }
    return fminf(o, mx);
}

__device__ __forceinline__ float f2tf32f(float x) {
    uint32_t r;
    asm("cvt.rna.tf32.f32 %0, %1;" : "=r"(r) : "f"(x));
    return __uint_as_float(r);
}

__device__ __forceinline__ void mma_tf32(float* d,
                                         float a0, float a1, float a2, float a3,
                                         float b0, float b1) {
    asm volatile(
        "mma.sync.aligned.m16n8k8.row.col.f32.tf32.tf32.f32 "
        "{%0,%1,%2,%3}, {%4,%5,%6,%7}, {%8,%9}, {%0,%1,%2,%3};"
        : "+f"(d[0]), "+f"(d[1]), "+f"(d[2]), "+f"(d[3])
        : "r"(__float_as_uint(a0)), "r"(__float_as_uint(a1)),
          "r"(__float_as_uint(a2)), "r"(__float_as_uint(a3)),
          "r"(__float_as_uint(b0)), "r"(__float_as_uint(b1)));
}

// Fragment slot permutation (conflict-free LDS.128 consumer / STS.32 producer).
__device__ __forceinline__ int frag_sigma(int x, int ci) {
    const int r0 = x & 1;
    const int r12 = (x >> 1) & 3;
    return (r12 << 3) | (r0 << 2) | (ci ^ r12);
}

#define BLK 132
#define A_SSTRIDE (8 * BLK)      // per k-step s: 8 m-tiles
#define B_GSTRIDE (16 * BLK)     // per k-group g: 16 n-tiles
#define A_TILE_FLOATS (4 * A_SSTRIDE)    // 4224
#define B_TILE_FLOATS (2 * B_GSTRIDE)    // 4224
#define STAGE_FLOATS (2 * A_TILE_FLOATS + 2 * B_TILE_FLOATS)   // 16896
#define SMEM_BYTES (2 * STAGE_FLOATS * 4)                      // 135168

// hi/lo pre-splitter: y_hi = tf32(x), y_lo = tf32(x - y_hi)
__global__ void __launch_bounds__(256)
split_kernel(const float* __restrict__ src, float* __restrict__ hi,
             float* __restrict__ lo, int n4)
{
    const int i = blockIdx.x * blockDim.x + threadIdx.x;
    if (i >= n4) return;
    const float4 v = ((const float4*)src)[i];
    float4 h, l;
    h.x = f2tf32f(v.x); l.x = f2tf32f(v.x - h.x);
    h.y = f2tf32f(v.y); l.y = f2tf32f(v.y - h.y);
    h.z = f2tf32f(v.z); l.z = f2tf32f(v.z - h.z);
    h.w = f2tf32f(v.w); l.w = f2tf32f(v.w - h.w);
    ((float4*)hi)[i] = h;
    ((float4*)lo)[i] = l;
}

// C = act_clip(A @ W^T + bias); A and W pre-split into hi/lo tf32 parts.
// 3xTF32: hi*hi + hi*lo + lo*hi. CTA 128x128, BK=32, 2-stage smem pipeline.
__global__ void __launch_bounds__(256)
fused_layer_mma3(const float* __restrict__ Ah, const float* __restrict__ Al,
                 const float* __restrict__ Wh, const float* __restrict__ Wl,
                 const float* __restrict__ bias,
                 const int*   __restrict__ fid,
                 const float* __restrict__ mx,
                 float* __restrict__ Ch, float* __restrict__ Cl,
                 int N, int split_out)
{
    extern __shared__ __align__(16) float smem[];

    const int tid = threadIdx.x;
    const int w   = tid >> 5;
    const int l   = tid & 31;

    const int bn = blockIdx.x * 128;
    const int bm = blockIdx.y * 128;

    // ---- staging maps ----
    const int ar  = tid >> 1;       // A row 0..127
    const int ahk = tid & 1;        // k-half
    const int arr = ar & 15;
    const int atm = ar >> 4;
    const int areg = (arr >> 3) + 2 * ahk;
    int aslot[4];
    #pragma unroll
    for (int ci = 0; ci < 4; ++ci)
        aslot[ci] = atm * BLK + 4 * frag_sigma(arr & 7, ci) + areg;

    const int bj = tid & 3;
    const int bn0 = tid >> 2;       // 0..63
    int bslot[2][4];
    #pragma unroll
    for (int half = 0; half < 2; ++half) {
        const int n = bn0 + 64 * half;
        #pragma unroll
        for (int ci = 0; ci < 4; ++ci)
            bslot[half][ci] = (n >> 3) * BLK + 4 * frag_sigma(n & 7, ci) + bj;
    }

    const size_t aoff = (size_t)(bm + ar) * KDIM + ahk * 4;
    const float* Ahp = Ah + aoff;
    const float* Alp = Al + aoff;
    const size_t boff = (size_t)(bn + bn0) * KDIM + bj * 4;
    const float* Whp = Wh + boff;
    const float* Wlp = Wl + boff;

    // ---- consumer map ----
    const int wm = w & 3;
    const int wn = w >> 2;
    const int sig4 = 4 * frag_sigma(l >> 2, l & 3);

    float acc[2][8][4];
    #pragma unroll
    for (int i = 0; i < 2; ++i)
        #pragma unroll
        for (int u = 0; u < 8; ++u)
            #pragma unroll
            for (int r = 0; r < 4; ++r) acc[i][u][r] = 0.0f;

    float4 pah[4], pal[4], pbh[4], pbl[4];

    // A rep = k-step s: k = 32kc + 8s (+ 4ahk). B rep: half=rep>>1, g=rep&1: k = 32kc + 16g.
    #define LOAD_CHUNK(kc_) do {                                              \
        const int ko_ = (kc_) * 32;                                           \
        _Pragma("unroll")                                                     \
        for (int rep = 0; rep < 4; ++rep) {                                   \
            pah[rep] = *(const float4*)(Ahp + ko_ + rep * 8);                 \
            pal[rep] = *(const float4*)(Alp + ko_ + rep * 8);                 \
            const size_t bo_ = ((rep >> 1) ? (size_t)64 * KDIM : 0)           \
                               + ko_ + (rep & 1) * 16;                        \
            pbh[rep] = *(const float4*)(Whp + bo_);                           \
            pbl[rep] = *(const float4*)(Wlp + bo_);                           \
        }                                                                     \
    } while (0)

    #define STORE_CHUNK(dst_) do {                                           \
        float* d_ = (dst_);                                                   \
        _Pragma("unroll")                                                     \
        for (int rep = 0; rep < 4; ++rep) {                                   \
            float* ah_ = d_ + rep * A_SSTRIDE;                                \
            float* al_ = ah_ + A_TILE_FLOATS;                                 \
            const float* vah_ = &pah[rep].x;                                  \
            const float* val_ = &pal[rep].x;                                  \
            _Pragma("unroll")                                                 \
            for (int ci = 0; ci < 4; ++ci) {                                  \
                ah_[aslot[ci]] = vah_[ci];                                    \
                al_[aslot[ci]] = val_[ci];                                    \
            }                                                                 \
            float* bh_ = d_ + 2 * A_TILE_FLOATS + (rep & 1) * B_GSTRIDE;      \
            float* bl_ = bh_ + B_TILE_FLOATS;                                 \
            const int* bsl_ = bslot[rep >> 1];                                \
            const float* vbh_ = &pbh[rep].x;                                  \
            const float* vbl_ = &pbl[rep].x;                                  \
            _Pragma("unroll")                                                 \
            for (int ci = 0; ci < 4; ++ci) {                                  \
                bh_[bsl_[ci]] = vbh_[ci];                                     \
                bl_[bsl_[ci]] = vbl_[ci];                                     \
            }                                                                 \
        }                                                                     \
    } while (0)

    // prologue: stage chunk 0
    LOAD_CHUNK(0);
    STORE_CHUNK(smem);
    __syncthreads();

    constexpr int NCHUNK = KDIM / 32;   // 16
    for (int kc = 0; kc < NCHUNK; ++kc) {
        const int st = kc & 1;
        float* base = smem + st * STAGE_FLOATS;
        float* sAh = base;
        float* sAl = base + A_TILE_FLOATS;
        float* sBh = base + 2 * A_TILE_FLOATS;
        float* sBl = sBh + B_TILE_FLOATS;

        if (kc + 1 < NCHUNK) LOAD_CHUNK(kc + 1);   // LDG covered by mma below

        #pragma unroll
        for (int g = 0; g < 2; ++g) {
            #pragma unroll
            for (int un = 0; un < 2; ++un) {
                float4 bqh[4], bql[4];
                #pragma unroll
                for (int uq = 0; uq < 4; ++uq) {
                    const int u = wn * 8 + un * 4 + uq;
                    bqh[uq] = *(const float4*)&sBh[(g * 16 + u) * BLK + sig4];
                    bql[uq] = *(const float4*)&sBl[(g * 16 + u) * BLK + sig4];
                }
                #pragma unroll
                for (int p = 0; p < 2; ++p) {
                    const int s = 2 * g + p;
                    const int abase0 = (s * 8 + 2 * wm + 0) * BLK + sig4;
                    const int abase1 = (s * 8 + 2 * wm + 1) * BLK + sig4;
                    const float4 ah0 = *(const float4*)&sAh[abase0];
                    const float4 ah1 = *(const float4*)&sAh[abase1];
                    const float4 al0 = *(const float4*)&sAl[abase0];
                    const float4 al1 = *(const float4*)&sAl[abase1];
                    #pragma unroll
                    for (int uq = 0; uq < 4; ++uq) {
                        const float b0h = p ? bqh[uq].z : bqh[uq].x;
                        const float b1h = p ? bqh[uq].w : bqh[uq].y;
                        const float b0l = p ? bql[uq].z : bql[uq].x;
                        const float b1l = p ? bql[uq].w : bql[uq].y;
                        float* a0 = acc[0][un * 4 + uq];
                        float* a1 = acc[1][un * 4 + uq];
                        mma_tf32(a0, ah0.x, ah0.y, ah0.z, ah0.w, b0h, b1h);
                        mma_tf32(a0, ah0.x, ah0.y, ah0.z, ah0.w, b0l, b1l);
                        mma_tf32(a0, al0.x, al0.y, al0.z, al0.w, b0h, b1h);
                        mma_tf32(a1, ah1.x, ah1.y, ah1.z, ah1.w, b0h, b1h);
                        mma_tf32(a1, ah1.x, ah1.y, ah1.z, ah1.w, b0l, b1l);
                        mma_tf32(a1, al1.x, al1.y, al1.z, al1.w, b0h, b1h);
                    }
                }
            }
        }

        if (kc + 1 < NCHUNK) STORE_CHUNK(smem + (st ^ 1) * STAGE_FLOATS);
        __syncthreads();
    }

    // ---- epilogue: bias + per-column activation + clip (+ optional hi/lo emit) ----
    #pragma unroll
    for (int uu = 0; uu < 8; ++uu) {
        const int col = bn + wn * 64 + uu * 8 + (l & 3) * 2;
        const float bv0 = __ldg(bias + col);
        const float bv1 = __ldg(bias + col + 1);
        const int   f0  = __ldg(fid + col);
        const int   f1  = __ldg(fid + col + 1);
        const float m0  = __ldg(mx + col);
        const float m1  = __ldg(mx + col + 1);
        #pragma unroll
        for (int i = 0; i < 2; ++i) {
            const int row0 = bm + wm * 32 + i * 16 + (l >> 2);
            const float* a4 = acc[i][uu];
            float v00 = act_clip(a4[0] + bv0, f0, m0);
            float v01 = act_clip(a4[1] + bv1, f1, m1);
            float v10 = act_clip(a4[2] + bv0, f0, m0);
            float v11 = act_clip(a4[3] + bv1, f1, m1);
            if (split_out) {
                float h00 = f2tf32f(v00), h01 = f2tf32f(v01);
                float h10 = f2tf32f(v10), h11 = f2tf32f(v11);
                *(float2*)(Ch + (size_t)row0 * N + col)       = make_float2(h00, h01);
                *(float2*)(Ch + (size_t)(row0 + 8) * N + col) = make_float2(h10, h11);
                *(float2*)(Cl + (size_t)row0 * N + col)       =
                    make_float2(f2tf32f(v00 - h00), f2tf32f(v01 - h01));
                *(float2*)(Cl + (size_t)(row0 + 8) * N + col) =
                    make_float2(f2tf32f(v10 - h10), f2tf32f(v11 - h11));
            } else {
                *(float2*)(Ch + (size_t)row0 * N + col)       = make_float2(v00, v01);
                *(float2*)(Ch + (size_t)(row0 + 8) * N + col) = make_float2(v10, v11);
            }
        }
    }
}

extern "C" void kernel_launch(void* const* d_in, const int* in_sizes, int n_in,
                              void* d_out, int out_size) {
    const float* x      = (const float*)d_in[0];   // [65536, 512]
    const float* W_in   = (const float*)d_in[1];   // [512, 512]
    const float* b_in   = (const float*)d_in[2];   // [512]
    const float* W_h    = (const float*)d_in[3];   // [4, 512, 512]
    const float* b_h    = (const float*)d_in[4];   // [4, 512]
    const float* W_out  = (const float*)d_in[5];   // [128, 512]
    const float* b_out  = (const float*)d_in[6];   // [128]
    const float* m_in   = (const float*)d_in[7];   // [512]
    const float* m_h    = (const float*)d_in[8];   // [4, 512]
    const float* m_out  = (const float*)d_in[9];   // [128]
    const int*   fid_in = (const int*)d_in[10];    // [512]
    const int*   fid_h  = (const int*)d_in[11];    // [4, 512]
    const int*   fid_out= (const int*)d_in[12];    // [128]
    float* out = (float*)d_out;                    // [65536, 128]

    float *hiA, *loA, *hiB, *loB, *Wh, *Wl;
    cudaGetSymbolAddress((void**)&hiA, g_hiA);
    cudaGetSymbolAddress((void**)&loA, g_loA);
    cudaGetSymbolAddress((void**)&hiB, g_hiB);
    cudaGetSymbolAddress((void**)&loB, g_loB);
    cudaGetSymbolAddress((void**)&Wh, g_Wh);
    cudaGetSymbolAddress((void**)&Wl, g_Wl);

    cudaFuncSetAttribute(fused_layer_mma3,
                         cudaFuncAttributeMaxDynamicSharedMemorySize, SMEM_BYTES);

    // --- pre-split input + weights into tf32 hi/lo ---
    {
        const int n4_in = B_TOTAL * KDIM / 4;           // 8388608
        split_kernel<<<n4_in / 256, 256>>>(x, hiA, loA, n4_in);
        const int n4_win = 512 * 512 / 4;               // 65536
        split_kernel<<<n4_win / 256, 256>>>(W_in, Wh, Wl, n4_win);
        const int n4_wh = 4 * 512 * 512 / 4;            // 262144
        split_kernel<<<n4_wh / 256, 256>>>(W_h, Wh + 262144, Wl + 262144, n4_wh);
        const int n4_wo = 128 * 512 / 4;                // 16384
        split_kernel<<<n4_wo / 256, 256>>>(W_out, Wh + 1310720, Wl + 1310720, n4_wo);
    }

    dim3 blk(256);
    dim3 g512(512 / 128, B_TOTAL / 128);
    dim3 g128(128 / 128, B_TOTAL / 128);

    // input layer: (hiA,loA) -> (hiB,loB)
    fused_layer_mma3<<<g512, blk, SMEM_BYTES>>>(hiA, loA, Wh, Wl,
                                                b_in, fid_in, m_in,
                                                hiB, loB, 512, 1);

    // 4 hidden layers, ping-pong
    const float* curH = hiB; const float* curL = loB;
    float* nxtH = hiA;       float* nxtL = loA;
    for (int i = 0; i < 4; ++i) {
        const size_t woff = 262144 + (size_t)i * 262144;
        fused_layer_mma3<<<g512, blk, SMEM_BYTES>>>(curH, curL,
                                                    Wh + woff, Wl + woff,
                                                    b_h + i * 512,
                                                    fid_h + i * 512,
                                                    m_h + i * 512,
                                                    nxtH, nxtL, 512, 1);
        float* tH = nxtH; float* tL = nxtL;
        nxtH = (float*)curH; nxtL = (float*)curL;
        curH = tH; curL = tL;
    }

    // output layer: plain fp32 out, no split
    fused_layer_mma3<<<g128, blk, SMEM_BYTES>>>(curH, curL,
                                                Wh + 1310720, Wl + 1310720,
                                                b_out, fid_out, m_out,
                                                out, nullptr, 128, 0);
}

// round 9
// speedup vs baseline: 1.2264x; 1.2264x over previous
#include <cuda_runtime.h>
#include <cstdint>
#include <math.h>

#define B_TOTAL 65536
#define KDIM 512
// Packed weights: W_in (4 nblk) + 4x W_h (4 nblk each) + W_out (1 nblk), 16 chunks x 4096 floats per nblk
#define W_TOTAL (262144 * 5 + 65536)

__device__ float g_hiA[(size_t)B_TOTAL * KDIM];
__device__ float g_loA[(size_t)B_TOTAL * KDIM];
__device__ float g_hiB[(size_t)B_TOTAL * KDIM];
__device__ float g_loB[(size_t)B_TOTAL * KDIM];
__device__ float g_Wh[W_TOTAL];
__device__ float g_Wl[W_TOTAL];

__device__ __forceinline__ float act_clip(float h, int f, float mx) {
    float o;
    if (f == 0) {
        o = fmaxf(h, 0.0f);                       // ReLU
    } else if (f == 1) {
        o = 1.0f / (1.0f + __expf(-h));           // Sigmoid
    } else if (f == 2) {
        o = tanhf(h);                             // Tanh
    } else if (f == 3) {
        o = (h > 0.0f) ? h : 0.1f * h;            // LeakyReLU(0.1)
    } else {
        const float sc = 1.0507009873554805f;     // SELU
        const float al = 1.6732632423543772f;
        o = (h > 0.0f) ? sc * h : sc * al * (__expf(h) - 1.0f);
    }
    return fminf(o, mx);
}

__device__ __forceinline__ float f2tf32f(float x) {
    uint32_t r;
    asm("cvt.rna.tf32.f32 %0, %1;" : "=r"(r) : "f"(x));
    return __uint_as_float(r);
}

__device__ __forceinline__ void mma_tf32(float* d,
                                         float a0, float a1, float a2, float a3,
                                         float b0, float b1) {
    asm volatile(
        "mma.sync.aligned.m16n8k8.row.col.f32.tf32.tf32.f32 "
        "{%0,%1,%2,%3}, {%4,%5,%6,%7}, {%8,%9}, {%0,%1,%2,%3};"
        : "+f"(d[0]), "+f"(d[1]), "+f"(d[2]), "+f"(d[3])
        : "r"(__float_as_uint(a0)), "r"(__float_as_uint(a1)),
          "r"(__float_as_uint(a2)), "r"(__float_as_uint(a3)),
          "r"(__float_as_uint(b0)), "r"(__float_as_uint(b1)));
}

// Fragment granule permutation: (x = row&7, ci = k&3) -> granule index 0..31.
// sigma = (r12<<3) | (r0<<2) | (ci ^ r12), r0 = x&1, r12 = x>>1.
__device__ __forceinline__ int frag_sigma(int x, int ci) {
    const int r0 = x & 1;
    const int r12 = (x >> 1) & 3;
    return (r12 << 3) | (r0 << 2) | (ci ^ r12);
}

// Tile/stage geometry: chunk = BK=32. A tile: [s(4)][mt(8)][32 granules x 4] = 4096 floats.
// B tile: [g(2)][nt(16)][32 granules x 4] = 4096 floats.
// Stage: Ah | Al | Bh | Bl = 16384 floats = 64 KB. 3 stages = 192 KB.
#define CHUNK_FLOATS 4096
#define STAGE_FLOATS (4 * CHUNK_FLOATS)
#define NSTAGE 3
#define SMEM_BYTES (NSTAGE * STAGE_FLOATS * 4)

__device__ __forceinline__ void cp_async16(uint32_t dst, const float* src) {
    asm volatile("cp.async.cg.shared.global [%0], [%1], 16;" :: "r"(dst), "l"(src));
}

// ---- pack kernels: fp32 row-major -> packed tf32 hi/lo fragment layout ----

// A layout (per m_blk of 128 rows): idx = ((((m_blk*16 + kc)*4 + s)*8 + mt)*32 + gran)*4 + pos
// pos = r8 + 2*khalf; element = A[m_blk*128 + mt*16 + r8*8 + x][kc*32 + s*8 + khalf*4 + ci]
__global__ void __launch_bounds__(256)
pack_a(const float* __restrict__ src, float* __restrict__ hi, float* __restrict__ lo)
{
    const size_t gid = (size_t)blockIdx.x * 256 + threadIdx.x;  // granule index
    size_t t = gid;
    const int gran = t & 31; t >>= 5;
    const int mt   = t & 7;  t >>= 3;
    const int s    = t & 3;  t >>= 2;
    const int kc   = t & 15; t >>= 4;
    const int m_blk = (int)t;
    const int r12 = gran >> 3, r0 = (gran >> 2) & 1;
    const int ci = (gran & 3) ^ r12;
    const int x  = r12 * 2 + r0;
    const int row = m_blk * 128 + mt * 16 + x;
    const int k0  = kc * 32 + s * 8 + ci;
    const float v0 = src[(size_t)row * KDIM + k0];           // pos0: r8=0, khalf=0
    const float v1 = src[(size_t)(row + 8) * KDIM + k0];     // pos1: r8=1
    const float v2 = src[(size_t)row * KDIM + k0 + 4];       // pos2: khalf=1
    const float v3 = src[(size_t)(row + 8) * KDIM + k0 + 4]; // pos3
    float4 h, l;
    h.x = f2tf32f(v0); l.x = f2tf32f(v0 - h.x);
    h.y = f2tf32f(v1); l.y = f2tf32f(v1 - h.y);
    h.z = f2tf32f(v2); l.z = f2tf32f(v2 - h.z);
    h.w = f2tf32f(v3); l.w = f2tf32f(v3 - h.w);
    ((float4*)hi)[gid] = h;
    ((float4*)lo)[gid] = l;
}

// B layout (per n_blk of 128 rows): idx = ((((n_blk*16 + kc)*2 + g)*16 + nt)*32 + gran)*4 + j
// element = W[n_blk*128 + nt*8 + x][kc*32 + g*16 + j*4 + ci]
__global__ void __launch_bounds__(256)
pack_w(const float* __restrict__ src, float* __restrict__ hi, float* __restrict__ lo)
{
    const size_t gid = (size_t)blockIdx.x * 256 + threadIdx.x;
    size_t t = gid;
    const int gran = t & 31; t >>= 5;
    const int nt   = t & 15; t >>= 4;
    const int g    = t & 1;  t >>= 1;
    const int kc   = t & 15; t >>= 4;
    const int n_blk = (int)t;
    const int r12 = gran >> 3, r0 = (gran >> 2) & 1;
    const int ci = (gran & 3) ^ r12;
    const int x  = r12 * 2 + r0;
    const int n  = n_blk * 128 + nt * 8 + x;
    const int k0 = kc * 32 + g * 16 + ci;
    float4 h, l;
    float v;
    v = src[(size_t)n * KDIM + k0];      h.x = f2tf32f(v); l.x = f2tf32f(v - h.x);
    v = src[(size_t)n * KDIM + k0 + 4];  h.y = f2tf32f(v); l.y = f2tf32f(v - h.y);
    v = src[(size_t)n * KDIM + k0 + 8];  h.z = f2tf32f(v); l.z = f2tf32f(v - h.z);
    v = src[(size_t)n * KDIM + k0 + 12]; h.w = f2tf32f(v); l.w = f2tf32f(v - h.w);
    ((float4*)hi)[gid] = h;
    ((float4*)lo)[gid] = l;
}

// ---- fused 3xTF32 GEMM layer ----
// A, W packed hi/lo. CTA 128x128 tile, BK=32, 3-stage cp.async pipeline.
// split_out=1: write packed hi/lo activations (next layer's A).
// split_out=0: write plain fp32 row-major [*, Nout] to Cout.
__global__ void __launch_bounds__(256)
fused_layer_mma3(const float* __restrict__ Ah, const float* __restrict__ Al,
                 const float* __restrict__ Bh, const float* __restrict__ Bl,
                 const float* __restrict__ bias,
                 const int*   __restrict__ fid,
                 const float* __restrict__ mx,
                 float* __restrict__ Ch, float* __restrict__ Cl,
                 int Nout, int split_out)
{
    extern __shared__ __align__(16) float smem[];

    const int tid = threadIdx.x;
    const int w   = tid >> 5;
    const int l   = tid & 31;
    const int bn  = blockIdx.x * 128;

    const uint32_t smem_u32 = (uint32_t)__cvta_generic_to_shared(smem);

    const size_t a_base = (size_t)blockIdx.y * 16 * CHUNK_FLOATS;
    const size_t b_base = (size_t)blockIdx.x * 16 * CHUNK_FLOATS;

    // ---- consumer map ----
    const int wm = w & 3;
    const int wn = w >> 2;
    const int sig4 = 4 * frag_sigma(l >> 2, l & 3);

    float acc[2][8][4];
    #pragma unroll
    for (int i = 0; i < 2; ++i)
        #pragma unroll
        for (int u = 0; u < 8; ++u)
            #pragma unroll
            for (int r = 0; r < 4; ++r) acc[i][u][r] = 0.0f;

    // issue one chunk's cp.async copies (16 x 16B per thread) + commit
    #define ISSUE_CHUNK(kc_) do {                                             \
        const uint32_t dst_ = smem_u32 + ((kc_) % NSTAGE) * (STAGE_FLOATS*4); \
        const float* pa_h = Ah + a_base + (size_t)(kc_) * CHUNK_FLOATS;       \
        const float* pa_l = Al + a_base + (size_t)(kc_) * CHUNK_FLOATS;       \
        const float* pb_h = Bh + b_base + (size_t)(kc_) * CHUNK_FLOATS;       \
        const float* pb_l = Bl + b_base + (size_t)(kc_) * CHUNK_FLOATS;       \
        _Pragma("unroll")                                                     \
        for (int j = 0; j < 4; ++j) {                                         \
            const int g4 = (tid + j * 256) * 4;                               \
            cp_async16(dst_ + (0 * CHUNK_FLOATS + g4) * 4, pa_h + g4);        \
            cp_async16(dst_ + (1 * CHUNK_FLOATS + g4) * 4, pa_l + g4);        \
            cp_async16(dst_ + (2 * CHUNK_FLOATS + g4) * 4, pb_h + g4);        \
            cp_async16(dst_ + (3 * CHUNK_FLOATS + g4) * 4, pb_l + g4);        \
        }                                                                     \
        asm volatile("cp.async.commit_group;" ::: "memory");                  \
    } while (0)

    ISSUE_CHUNK(0);
    ISSUE_CHUNK(1);
    ISSUE_CHUNK(2);

    constexpr int NCHUNK = KDIM / 32;   // 16
    for (int kc = 0; kc < NCHUNK; ++kc) {
        asm volatile("cp.async.wait_group 2;" ::: "memory");
        __syncthreads();

        const float* base = smem + (kc % NSTAGE) * STAGE_FLOATS;
        const float* sAh = base;
        const float* sAl = base + CHUNK_FLOATS;
        const float* sBh = base + 2 * CHUNK_FLOATS;
        const float* sBl = base + 3 * CHUNK_FLOATS;

        #pragma unroll
        for (int g = 0; g < 2; ++g) {
            #pragma unroll
            for (int un = 0; un < 2; ++un) {
                float4 bqh[4], bql[4];
                #pragma unroll
                for (int uq = 0; uq < 4; ++uq) {
                    const int u = wn * 8 + un * 4 + uq;
                    bqh[uq] = *(const float4*)&sBh[(g * 16 + u) * 128 + sig4];
                    bql[uq] = *(const float4*)&sBl[(g * 16 + u) * 128 + sig4];
                }
                #pragma unroll
                for (int p = 0; p < 2; ++p) {
                    const int s = 2 * g + p;
                    const int abase0 = (s * 8 + 2 * wm + 0) * 128 + sig4;
                    const int abase1 = (s * 8 + 2 * wm + 1) * 128 + sig4;
                    const float4 ah0 = *(const float4*)&sAh[abase0];
                    const float4 ah1 = *(const float4*)&sAh[abase1];
                    const float4 al0 = *(const float4*)&sAl[abase0];
                    const float4 al1 = *(const float4*)&sAl[abase1];
                    #pragma unroll
                    for (int uq = 0; uq < 4; ++uq) {
                        const float b0h = p ? bqh[uq].z : bqh[uq].x;
                        const float b1h = p ? bqh[uq].w : bqh[uq].y;
                        const float b0l = p ? bql[uq].z : bql[uq].x;
                        const float b1l = p ? bql[uq].w : bql[uq].y;
                        float* a0 = acc[0][un * 4 + uq];
                        float* a1 = acc[1][un * 4 + uq];
                        // 3xTF32: hi*hi + hi*lo + lo*hi
                        mma_tf32(a0, ah0.x, ah0.y, ah0.z, ah0.w, b0h, b1h);
                        mma_tf32(a0, ah0.x, ah0.y, ah0.z, ah0.w, b0l, b1l);
                        mma_tf32(a0, al0.x, al0.y, al0.z, al0.w, b0h, b1h);
                        mma_tf32(a1, ah1.x, ah1.y, ah1.z, ah1.w, b0h, b1h);
                        mma_tf32(a1, ah1.x, ah1.y, ah1.z, ah1.w, b0l, b1l);
                        mma_tf32(a1, al1.x, al1.y, al1.z, al1.w, b0h, b1h);
                    }
                }
            }
        }
        __syncthreads();

        if (kc + NSTAGE < NCHUNK) {
            ISSUE_CHUNK(kc + NSTAGE);
        } else {
            asm volatile("cp.async.commit_group;" ::: "memory");
        }
    }

    // ---- epilogue ----
    const int xrow = l >> 2;            // row & 7
    #pragma unroll
    for (int uu = 0; uu < 8; ++uu) {
        const int col = bn + wn * 64 + uu * 8 + (l & 3) * 2;
        const float bv0 = __ldg(bias + col);
        const float bv1 = __ldg(bias + col + 1);
        const int   f0  = __ldg(fid + col);
        const int   f1  = __ldg(fid + col + 1);
        const float m0  = __ldg(mx + col);
        const float m1  = __ldg(mx + col + 1);
        if (split_out) {
            // packed write: col -> (kc, s, khalf, ci)
            const int kc   = col >> 5;
            const int s    = (col >> 3) & 3;
            const int kh2  = ((col >> 2) & 1) * 2;
            const int ci0  = col & 3;
            const int g0   = frag_sigma(xrow, ci0);
            const int g1   = frag_sigma(xrow, ci0 + 1);
            #pragma unroll
            for (int i = 0; i < 2; ++i) {
                const size_t base =
                    ((((size_t)blockIdx.y * 16 + kc) * 4 + s) * 8 + (2 * wm + i)) * 128;
                const float* a4 = acc[i][uu];
                const float v00 = act_clip(a4[0] + bv0, f0, m0);  // (r8=0, ci0)
                const float v01 = act_clip(a4[1] + bv1, f1, m1);  // (r8=0, ci0+1)
                const float v10 = act_clip(a4[2] + bv0, f0, m0);  // (r8=1, ci0)
                const float v11 = act_clip(a4[3] + bv1, f1, m1);  // (r8=1, ci0+1)
                const size_t i00 = base + 4 * g0 + 0 + kh2;
                const size_t i01 = base + 4 * g1 + 0 + kh2;
                const size_t i10 = base + 4 * g0 + 1 + kh2;
                const size_t i11 = base + 4 * g1 + 1 + kh2;
                const float h00 = f2tf32f(v00), h01 = f2tf32f(v01);
                const float h10 = f2tf32f(v10), h11 = f2tf32f(v11);
                Ch[i00] = h00; Cl[i00] = f2tf32f(v00 - h00);
                Ch[i01] = h01; Cl[i01] = f2tf32f(v01 - h01);
                Ch[i10] = h10; Cl[i10] = f2tf32f(v10 - h10);
                Ch[i11] = h11; Cl[i11] = f2tf32f(v11 - h11);
            }
        } else {
            #pragma unroll
            for (int i = 0; i < 2; ++i) {
                const int row0 = blockIdx.y * 128 + wm * 32 + i * 16 + xrow;
                const float* a4 = acc[i][uu];
                float2 v0, v1;
                v0.x = act_clip(a4[0] + bv0, f0, m0);
                v0.y = act_clip(a4[1] + bv1, f1, m1);
                v1.x = act_clip(a4[2] + bv0, f0, m0);
                v1.y = act_clip(a4[3] + bv1, f1, m1);
                *(float2*)(Ch + (size_t)row0 * Nout + col)       = v0;
                *(float2*)(Ch + (size_t)(row0 + 8) * Nout + col) = v1;
            }
        }
    }
}

extern "C" void kernel_launch(void* const* d_in, const int* in_sizes, int n_in,
                              void* d_out, int out_size) {
    const float* x      = (const float*)d_in[0];   // [65536, 512]
    const float* W_in   = (const float*)d_in[1];   // [512, 512]
    const float* b_in   = (const float*)d_in[2];   // [512]
    const float* W_h    = (const float*)d_in[3];   // [4, 512, 512]
    const float* b_h    = (const float*)d_in[4];   // [4, 512]
    const float* W_out  = (const float*)d_in[5];   // [128, 512]
    const float* b_out  = (const float*)d_in[6];   // [128]
    const float* m_in   = (const float*)d_in[7];   // [512]
    const float* m_h    = (const float*)d_in[8];   // [4, 512]
    const float* m_out  = (const float*)d_in[9];   // [128]
    const int*   fid_in = (const int*)d_in[10];    // [512]
    const int*   fid_h  = (const int*)d_in[11];    // [4, 512]
    const int*   fid_out= (const int*)d_in[12];    // [128]
    float* out = (float*)d_out;                    // [65536, 128]

    float *hiA, *loA, *hiB, *loB, *Wh, *Wl;
    cudaGetSymbolAddress((void**)&hiA, g_hiA);
    cudaGetSymbolAddress((void**)&loA, g_loA);
    cudaGetSymbolAddress((void**)&hiB, g_hiB);
    cudaGetSymbolAddress((void**)&loB, g_loB);
    cudaGetSymbolAddress((void**)&Wh, g_Wh);
    cudaGetSymbolAddress((void**)&Wl, g_Wl);

    cudaFuncSetAttribute(fused_layer_mma3,
                         cudaFuncAttributeMaxDynamicSharedMemorySize, SMEM_BYTES);

    // ---- one-time packing: x + all weights -> tf32 hi/lo fragment layout ----
    pack_a<<<(B_TOTAL * KDIM / 4) / 256, 256>>>(x, hiA, loA);
    pack_w<<<(4  * 16 * 2 * 16 * 32) / 256, 256>>>(W_in,  Wh,           Wl);
    pack_w<<<(16 * 16 * 2 * 16 * 32) / 256, 256>>>(W_h,   Wh + 262144,  Wl + 262144);
    pack_w<<<(1  * 16 * 2 * 16 * 32) / 256, 256>>>(W_out, Wh + 1310720, Wl + 1310720);

    dim3 blk(256);
    dim3 g512(4, B_TOTAL / 128);   // 4 n_blks x 512 m_blks
    dim3 g128(1, B_TOTAL / 128);

    // input layer: packed (hiA,loA) -> packed (hiB,loB)
    fused_layer_mma3<<<g512, blk, SMEM_BYTES>>>(hiA, loA, Wh, Wl,
                                                b_in, fid_in, m_in,
                                                hiB, loB, 512, 1);

    // 4 hidden layers, ping-pong
    const float* curH = hiB; const float* curL = loB;
    float* nxtH = hiA;       float* nxtL = loA;
    for (int i = 0; i < 4; ++i) {
        const size_t woff = 262144 + (size_t)i * 262144;
        fused_layer_mma3<<<g512, blk, SMEM_BYTES>>>(curH, curL,
                                                    Wh + woff, Wl + woff,
                                                    b_h + i * 512,
                                                    fid_h + i * 512,
                                                    m_h + i * 512,
                                                    nxtH, nxtL, 512, 1);
        float* tH = nxtH; float* tL = nxtL;
        nxtH = (float*)curH; nxtL = (float*)curL;
        curH = tH; curL = tL;
    }

    // output layer: plain fp32 row-major out
    fused_layer_mma3<<<g128, blk, SMEM_BYTES>>>(curH, curL,
                                                Wh + 1310720, Wl + 1310720,
                                                b_out, fid_out, m_out,
                                                out, nullptr, 128, 0);
}

// round 11
// speedup vs baseline: 2.8246x; 2.3031x over previous
#include <cuda_runtime.h>
#include <cuda_fp16.h>
#include <cstdint>
#include <math.h>

#define B_TOTAL 65536
#define KDIM 512

// Packed fp16 limb layout.
// A (per m_blk of 128 rows): word idx = ((((m_blk*16+kc)*2+k16)*8+mt)*32+lane)*4 + r
//   lane: g=lane>>2, tig=lane&3.  reg r: row = mt*16+g+8*(r&1), k = kc*32+k16*16+tig*2+8*(r>>1), halves k,k+1
// B (per n_blk of 128 cols): word idx = ((((n_blk*16+kc)*2+k16)*8+np)*32+lane)*4 + r
//   r0 = b0 of group u=np*2 (n=np*16+g, k=tig*2), r1 = b1 (k+8), r2/r3 same for group u+1 (n+8)
#define A_BLK_U4 8192              // uint4 per m_blk per limb (32768 words)
#define W_NBLK_U4 8192             // uint4 per n_blk per limb
#define CHUNK_REGION_WORDS 2048    // words per region per K32 chunk
#define NSTAGE 3
#define STAGE_WORDS (4 * CHUNK_REGION_WORDS)     // 8192 words = 32 KB
#define SMEM_BYTES (NSTAGE * STAGE_WORDS * 4)    // 96 KB

// Scratch (allocation-free): A limb ping-pong + packed weights (21 n_blks)
__device__ uint4 g_A0a[4194304];
__device__ uint4 g_A1a[4194304];
__device__ uint4 g_A0b[4194304];
__device__ uint4 g_A1b[4194304];
__device__ uint4 g_W0[21 * W_NBLK_U4];
__device__ uint4 g_W1[21 * W_NBLK_U4];

__device__ __forceinline__ float act_clip(float h, int f, float mx) {
    float o;
    if (f == 0) {
        o = fmaxf(h, 0.0f);                       // ReLU
    } else if (f == 1) {
        o = 1.0f / (1.0f + __expf(-h));           // Sigmoid
    } else if (f == 2) {
        o = tanhf(h);                             // Tanh
    } else if (f == 3) {
        o = (h > 0.0f) ? h : 0.1f * h;            // LeakyReLU(0.1)
    } else {
        const float sc = 1.0507009873554805f;     // SELU
        const float al = 1.6732632423543772f;
        o = (h > 0.0f) ? sc * h : sc * al * (__expf(h) - 1.0f);
    }
    return fminf(o, mx);
}

// fp16 two-limb split of a float pair -> (h0 word, h1 word), low half = first element
__device__ __forceinline__ void split2(float x, float y, uint32_t& w0, uint32_t& w1) {
    const __half hx = __float2half_rn(x);
    const __half hy = __float2half_rn(y);
    const __half lx = __float2half_rn(x - __half2float(hx));
    const __half ly = __float2half_rn(y - __half2float(hy));
    w0 = (uint32_t)__half_as_ushort(hx) | ((uint32_t)__half_as_ushort(hy) << 16);
    w1 = (uint32_t)__half_as_ushort(lx) | ((uint32_t)__half_as_ushort(ly) << 16);
}

__device__ __forceinline__ void mma16(float* d, const uint4& a, uint32_t b0, uint32_t b1) {
    asm volatile(
        "mma.sync.aligned.m16n8k16.row.col.f32.f16.f16.f32 "
        "{%0,%1,%2,%3}, {%4,%5,%6,%7}, {%8,%9}, {%0,%1,%2,%3};"
        : "+f"(d[0]), "+f"(d[1]), "+f"(d[2]), "+f"(d[3])
        : "r"(a.x), "r"(a.y), "r"(a.z), "r"(a.w), "r"(b0), "r"(b1));
}

__device__ __forceinline__ void cp_async16(uint32_t dst, const void* src) {
    asm volatile("cp.async.cg.shared.global [%0], [%1], 16;" :: "r"(dst), "l"(src));
}

// ---- pack: fp32 row-major [rows, 512] -> fp16 limb fragment layout ----
// One thread per uint4 granule: 4,194,304 threads total (each consumes 8 floats).
__global__ void __launch_bounds__(256)
pack_a16(const float* __restrict__ src, uint4* __restrict__ d0, uint4* __restrict__ d1)
{
    const uint32_t gid = blockIdx.x * 256 + threadIdx.x;   // 4,194,304 total
    const int lane = gid & 31;
    const int mt   = (gid >> 5) & 7;
    const int k16  = (gid >> 8) & 1;
    const int kc   = (gid >> 9) & 15;
    const int mblk = gid >> 13;
    const int g = lane >> 2, tig = lane & 3;
    const int row0 = mblk * 128 + mt * 16 + g;
    const int k0 = kc * 32 + k16 * 16 + tig * 2;
    const float2 p00 = *(const float2*)(src + (size_t)row0 * KDIM + k0);
    const float2 p10 = *(const float2*)(src + (size_t)(row0 + 8) * KDIM + k0);
    const float2 p01 = *(const float2*)(src + (size_t)row0 * KDIM + k0 + 8);
    const float2 p11 = *(const float2*)(src + (size_t)(row0 + 8) * KDIM + k0 + 8);
    uint4 h, l;
    split2(p00.x, p00.y, h.x, l.x);   // a0: (row g,   k..k+1)
    split2(p10.x, p10.y, h.y, l.y);   // a1: (row g+8, k..k+1)
    split2(p01.x, p01.y, h.z, l.z);   // a2: (row g,   k+8..k+9)
    split2(p11.x, p11.y, h.w, l.w);   // a3: (row g+8, k+8..k+9)
    d0[gid] = h;
    d1[gid] = l;
}

__global__ void __launch_bounds__(256)
pack_w16(const float* __restrict__ src, uint4* __restrict__ d0, uint4* __restrict__ d1)
{
    const uint32_t gid = blockIdx.x * 256 + threadIdx.x;
    const int lane = gid & 31;
    const int np   = (gid >> 5) & 7;
    const int k16  = (gid >> 8) & 1;
    const int kc   = (gid >> 9) & 15;
    const int nblk = gid >> 13;
    const int g = lane >> 2, tig = lane & 3;
    const int n0 = nblk * 128 + np * 16 + g;     // group u = np*2
    const int k0 = kc * 32 + k16 * 16 + tig * 2;
    const float2 q00 = *(const float2*)(src + (size_t)n0 * KDIM + k0);
    const float2 q01 = *(const float2*)(src + (size_t)n0 * KDIM + k0 + 8);
    const float2 q10 = *(const float2*)(src + (size_t)(n0 + 8) * KDIM + k0);
    const float2 q11 = *(const float2*)(src + (size_t)(n0 + 8) * KDIM + k0 + 8);
    uint4 h, l;
    split2(q00.x, q00.y, h.x, l.x);   // b0 of group u
    split2(q01.x, q01.y, h.y, l.y);   // b1 of group u
    split2(q10.x, q10.y, h.z, l.z);   // b0 of group u+1
    split2(q11.x, q11.y, h.w, l.w);   // b1 of group u+1
    d0[gid] = h;
    d1[gid] = l;
}

// ---- fused fp16x2-limb GEMM layer: act_clip(A @ W^T + bias) ----
// CTA 128x128 tile, BK=32, 3-stage cp.async pipeline, 8 warps of 32x64.
__global__ void __launch_bounds__(256)
fused_layer16(const uint4* __restrict__ A0, const uint4* __restrict__ A1,
              const uint4* __restrict__ B0, const uint4* __restrict__ B1,
              const float* __restrict__ bias,
              const int*   __restrict__ fid,
              const float* __restrict__ mx,
              uint32_t* __restrict__ C0, uint32_t* __restrict__ C1,
              float* __restrict__ Cout,
              int Nout, int split_out)
{
    extern __shared__ __align__(16) uint32_t smw[];

    const int tid = threadIdx.x;
    const int w   = tid >> 5;
    const int l   = tid & 31;
    const int bn  = blockIdx.x * 128;
    const int wm  = w & 3;            // m block (rows wm*32)
    const int wn  = w >> 2;           // n half (cols wn*64)

    const uint32_t smem_addr = (uint32_t)__cvta_generic_to_shared(smw);
    const size_t a_base = (size_t)blockIdx.y * A_BLK_U4;
    const size_t b_base = (size_t)blockIdx.x * W_NBLK_U4;

    float acc[2][8][4];
    #pragma unroll
    for (int i = 0; i < 2; ++i)
        #pragma unroll
        for (int u = 0; u < 8; ++u)
            #pragma unroll
            for (int r = 0; r < 4; ++r) acc[i][u][r] = 0.0f;

    #define ISSUE_CHUNK(kc_) do {                                             \
        const uint32_t dstb = smem_addr + ((kc_) % NSTAGE) * (STAGE_WORDS*4); \
        const uint4* pA0 = A0 + a_base + (size_t)(kc_) * 512;                 \
        const uint4* pA1 = A1 + a_base + (size_t)(kc_) * 512;                 \
        const uint4* pB0 = B0 + b_base + (size_t)(kc_) * 512;                 \
        const uint4* pB1 = B1 + b_base + (size_t)(kc_) * 512;                 \
        _Pragma("unroll")                                                     \
        for (int j = 0; j < 2; ++j) {                                         \
            const int g16 = tid + j * 256;                                    \
            cp_async16(dstb +         g16 * 16, pA0 + g16);                   \
            cp_async16(dstb +  8192 + g16 * 16, pA1 + g16);                   \
            cp_async16(dstb + 16384 + g16 * 16, pB0 + g16);                   \
            cp_async16(dstb + 24576 + g16 * 16, pB1 + g16);                   \
        }                                                                     \
        asm volatile("cp.async.commit_group;" ::: "memory");                  \
    } while (0)

    ISSUE_CHUNK(0);
    ISSUE_CHUNK(1);
    ISSUE_CHUNK(2);

    constexpr int NCHUNK = KDIM / 32;   // 16
    for (int kc = 0; kc < NCHUNK; ++kc) {
        asm volatile("cp.async.wait_group 2;" ::: "memory");
        __syncthreads();

        const uint32_t* sw = smw + (kc % NSTAGE) * STAGE_WORDS;
        #pragma unroll
        for (int k16 = 0; k16 < 2; ++k16) {
            const uint32_t* awb = sw + k16 * 1024;
            const uint4 ah0 = *(const uint4*)(awb + (wm * 2 + 0) * 128 + l * 4);
            const uint4 ah1 = *(const uint4*)(awb + (wm * 2 + 1) * 128 + l * 4);
            const uint4 al0 = *(const uint4*)(awb + 2048 + (wm * 2 + 0) * 128 + l * 4);
            const uint4 al1 = *(const uint4*)(awb + 2048 + (wm * 2 + 1) * 128 + l * 4);
            const uint32_t* bwb = sw + 4096 + k16 * 1024;
            #pragma unroll
            for (int pp = 0; pp < 4; ++pp) {
                const int np = wn * 4 + pp;
                const uint4 bh = *(const uint4*)(bwb + np * 128 + l * 4);
                const uint4 bl = *(const uint4*)(bwb + 2048 + np * 128 + l * 4);
                // group u = pp*2 (regs .x,.y), group u+1 (regs .z,.w)
                // acc += h0a*h0b + h0a*h1b + h1a*h0b
                mma16(acc[0][pp * 2],     ah0, bh.x, bh.y);
                mma16(acc[0][pp * 2],     ah0, bl.x, bl.y);
                mma16(acc[0][pp * 2],     al0, bh.x, bh.y);
                mma16(acc[1][pp * 2],     ah1, bh.x, bh.y);
                mma16(acc[1][pp * 2],     ah1, bl.x, bl.y);
                mma16(acc[1][pp * 2],     al1, bh.x, bh.y);
                mma16(acc[0][pp * 2 + 1], ah0, bh.z, bh.w);
                mma16(acc[0][pp * 2 + 1], ah0, bl.z, bl.w);
                mma16(acc[0][pp * 2 + 1], al0, bh.z, bh.w);
                mma16(acc[1][pp * 2 + 1], ah1, bh.z, bh.w);
                mma16(acc[1][pp * 2 + 1], ah1, bl.z, bl.w);
                mma16(acc[1][pp * 2 + 1], al1, bh.z, bh.w);
            }
        }
        __syncthreads();

        if (kc + NSTAGE < NCHUNK) {
            ISSUE_CHUNK(kc + NSTAGE);
        } else {
            asm volatile("cp.async.commit_group;" ::: "memory");
        }
    }

    // ---- epilogue ----
    const int g = l >> 2;
    #pragma unroll
    for (int u = 0; u < 8; ++u) {
        const int col = bn + wn * 64 + u * 8 + (l & 3) * 2;
        const float bv0 = __ldg(bias + col);
        const float bv1 = __ldg(bias + col + 1);
        const int   f0  = __ldg(fid + col);
        const int   f1  = __ldg(fid + col + 1);
        const float m0  = __ldg(mx + col);
        const float m1  = __ldg(mx + col + 1);
        #pragma unroll
        for (int i = 0; i < 2; ++i) {
            const float* a4 = acc[i][u];
            const float v00 = act_clip(a4[0] + bv0, f0, m0);  // (row g,   col)
            const float v01 = act_clip(a4[1] + bv1, f1, m1);  // (row g,   col+1)
            const float v10 = act_clip(a4[2] + bv0, f0, m0);  // (row g+8, col)
            const float v11 = act_clip(a4[3] + bv1, f1, m1);  // (row g+8, col+1)
            if (split_out) {
                // packed fp16-limb write for next layer's A
                const int kc_  = col >> 5;
                const int k16_ = (col >> 4) & 1;
                const int kb   = (col >> 3) & 1;
                const int mt_  = wm * 2 + i;
                const size_t wb =
                    ((((size_t)blockIdx.y * 16 + kc_) * 2 + k16_) * 8 + mt_) * 128
                    + (size_t)l * 4;
                uint32_t w0h, w0l, w1h, w1l;
                split2(v00, v01, w0h, w0l);
                split2(v10, v11, w1h, w1l);
                C0[wb + 2 * kb]     = w0h;  C1[wb + 2 * kb]     = w0l;
                C0[wb + 1 + 2 * kb] = w1h;  C1[wb + 1 + 2 * kb] = w1l;
            } else {
                const int row0 = blockIdx.y * 128 + wm * 32 + i * 16 + g;
                *(float2*)(Cout + (size_t)row0 * Nout + col)       = make_float2(v00, v01);
                *(float2*)(Cout + (size_t)(row0 + 8) * Nout + col) = make_float2(v10, v11);
            }
        }
    }
}

extern "C" void kernel_launch(void* const* d_in, const int* in_sizes, int n_in,
                              void* d_out, int out_size) {
    const float* x      = (const float*)d_in[0];   // [65536, 512]
    const float* W_in   = (const float*)d_in[1];   // [512, 512]
    const float* b_in   = (const float*)d_in[2];   // [512]
    const float* W_h    = (const float*)d_in[3];   // [4, 512, 512]
    const float* b_h    = (const float*)d_in[4];   // [4, 512]
    const float* W_out  = (const float*)d_in[5];   // [128, 512]
    const float* b_out  = (const float*)d_in[6];   // [128]
    const float* m_in   = (const float*)d_in[7];   // [512]
    const float* m_h    = (const float*)d_in[8];   // [4, 512]
    const float* m_out  = (const float*)d_in[9];   // [128]
    const int*   fid_in = (const int*)d_in[10];    // [512]
    const int*   fid_h  = (const int*)d_in[11];    // [4, 512]
    const int*   fid_out= (const int*)d_in[12];    // [128]
    float* out = (float*)d_out;                    // [65536, 128]

    uint4 *A0a, *A1a, *A0b, *A1b, *W0, *W1;
    cudaGetSymbolAddress((void**)&A0a, g_A0a);
    cudaGetSymbolAddress((void**)&A1a, g_A1a);
    cudaGetSymbolAddress((void**)&A0b, g_A0b);
    cudaGetSymbolAddress((void**)&A1b, g_A1b);
    cudaGetSymbolAddress((void**)&W0, g_W0);
    cudaGetSymbolAddress((void**)&W1, g_W1);

    cudaFuncSetAttribute(fused_layer16,
                         cudaFuncAttributeMaxDynamicSharedMemorySize, SMEM_BYTES);

    // ---- one-time packing into fp16 limb fragment layout ----
    // pack_a16: one thread per uint4 granule = 512 m_blks * 8192 = 4,194,304 threads
    pack_a16<<<16384, 256>>>(x, A0a, A1a);
    pack_w16<<<128, 256>>>(W_in,  W0,                W1);                   // 4 n_blks
    pack_w16<<<512, 256>>>(W_h,   W0 + 4 * W_NBLK_U4,  W1 + 4 * W_NBLK_U4); // 16 n_blks
    pack_w16<<<32, 256>>>(W_out,  W0 + 20 * W_NBLK_U4, W1 + 20 * W_NBLK_U4);// 1 n_blk

    dim3 blk(256);
    dim3 g512(4, B_TOTAL / 128);
    dim3 g128(1, B_TOTAL / 128);

    // input layer: packed A(a) -> packed A(b)
    fused_layer16<<<g512, blk, SMEM_BYTES>>>(A0a, A1a, W0, W1,
                                             b_in, fid_in, m_in,
                                             (uint32_t*)A0b, (uint32_t*)A1b,
                                             nullptr, 512, 1);

    // 4 hidden layers, ping-pong
    const uint4* c0 = A0b; const uint4* c1 = A1b;
    uint4* n0 = A0a;       uint4* n1 = A1a;
    for (int i = 0; i < 4; ++i) {
        const size_t woff = (size_t)(4 + 4 * i) * W_NBLK_U4;
        fused_layer16<<<g512, blk, SMEM_BYTES>>>(c0, c1, W0 + woff, W1 + woff,
                                                 b_h + i * 512,
                                                 fid_h + i * 512,
                                                 m_h + i * 512,
                                                 (uint32_t*)n0, (uint32_t*)n1,
                                                 nullptr, 512, 1);
        uint4* t0 = n0; uint4* t1 = n1;
        n0 = (uint4*)c0; n1 = (uint4*)c1;
        c0 = t0; c1 = t1;
    }

    // output layer: plain fp32 row-major out
    fused_layer16<<<g128, blk, SMEM_BYTES>>>(c0, c1,
                                             W0 + 20 * W_NBLK_U4, W1 + 20 * W_NBLK_U4,
                                             b_out, fid_out, m_out,
                                             nullptr, nullptr, out, 128, 0);
}

// round 12
// speedup vs baseline: 2.8400x; 1.0055x over previous
#include <cuda_runtime.h>
#include <cuda_fp16.h>
#include <cstdint>
#include <math.h>

#define B_TOTAL 65536
#define KDIM 512

// Packed fp16 limb layout.
// A (per m_blk of 128 rows): word idx = ((((m_blk*16+kc)*2+k16)*8+mt)*32+lane)*4 + r
//   lane: g=lane>>2, tig=lane&3.  reg r: row = mt*16+g+8*(r&1), k = kc*32+k16*16+tig*2+8*(r>>1), halves k,k+1
// B (per n_blk of 128 cols): word idx = ((((n_blk*16+kc)*2+k16)*8+np)*32+lane)*4 + r
//   r0 = b0 of group u=np*2 (n=np*16+g, k=tig*2), r1 = b1 (k+8), r2/r3 same for group u+1 (n+8)
#define A_BLK_U4 8192              // uint4 per m_blk per limb (32768 words)
#define W_NBLK_U4 8192             // uint4 per n_blk per limb
#define NSTAGE 3
#define STAGE_WORDS 8192                         // 32 KB per stage
#define SMEM_BYTES (NSTAGE * STAGE_WORDS * 4)    // 96 KB

// Scratch (allocation-free): A limb ping-pong + packed weights (21 n_blks)
__device__ uint4 g_A0a[4194304];
__device__ uint4 g_A1a[4194304];
__device__ uint4 g_A0b[4194304];
__device__ uint4 g_A1b[4194304];
__device__ uint4 g_W0[21 * W_NBLK_U4];
__device__ uint4 g_W1[21 * W_NBLK_U4];

__device__ __forceinline__ float act_clip(float h, int f, float mx) {
    float o;
    if (f == 0) {
        o = fmaxf(h, 0.0f);                       // ReLU
    } else if (f == 1) {
        o = 1.0f / (1.0f + __expf(-h));           // Sigmoid
    } else if (f == 2) {
        o = tanhf(h);                             // Tanh
    } else if (f == 3) {
        o = (h > 0.0f) ? h : 0.1f * h;            // LeakyReLU(0.1)
    } else {
        const float sc = 1.0507009873554805f;     // SELU
        const float al = 1.6732632423543772f;
        o = (h > 0.0f) ? sc * h : sc * al * (__expf(h) - 1.0f);
    }
    return fminf(o, mx);
}

// fp16 two-limb split of a float pair -> (h0 word, h1 word), low half = first element
__device__ __forceinline__ void split2(float x, float y, uint32_t& w0, uint32_t& w1) {
    const __half hx = __float2half_rn(x);
    const __half hy = __float2half_rn(y);
    const __half lx = __float2half_rn(x - __half2float(hx));
    const __half ly = __float2half_rn(y - __half2float(hy));
    w0 = (uint32_t)__half_as_ushort(hx) | ((uint32_t)__half_as_ushort(hy) << 16);
    w1 = (uint32_t)__half_as_ushort(lx) | ((uint32_t)__half_as_ushort(ly) << 16);
}

__device__ __forceinline__ void mma16(float* d, const uint4& a, uint32_t b0, uint32_t b1) {
    asm volatile(
        "mma.sync.aligned.m16n8k16.row.col.f32.f16.f16.f32 "
        "{%0,%1,%2,%3}, {%4,%5,%6,%7}, {%8,%9}, {%0,%1,%2,%3};"
        : "+f"(d[0]), "+f"(d[1]), "+f"(d[2]), "+f"(d[3])
        : "r"(a.x), "r"(a.y), "r"(a.z), "r"(a.w), "r"(b0), "r"(b1));
}

__device__ __forceinline__ void cp_async16(uint32_t dst, const void* src) {
    asm volatile("cp.async.cg.shared.global [%0], [%1], 16;" :: "r"(dst), "l"(src));
}

// ---- pack: fp32 row-major [rows, 512] -> fp16 limb fragment layout ----
// One thread per uint4 granule (each consumes 8 floats).
__global__ void __launch_bounds__(256)
pack_a16(const float* __restrict__ src, uint4* __restrict__ d0, uint4* __restrict__ d1)
{
    const uint32_t gid = blockIdx.x * 256 + threadIdx.x;   // 4,194,304 total
    const int lane = gid & 31;
    const int mt   = (gid >> 5) & 7;
    const int k16  = (gid >> 8) & 1;
    const int kc   = (gid >> 9) & 15;
    const int mblk = gid >> 13;
    const int g = lane >> 2, tig = lane & 3;
    const int row0 = mblk * 128 + mt * 16 + g;
    const int k0 = kc * 32 + k16 * 16 + tig * 2;
    const float2 p00 = *(const float2*)(src + (size_t)row0 * KDIM + k0);
    const float2 p10 = *(const float2*)(src + (size_t)(row0 + 8) * KDIM + k0);
    const float2 p01 = *(const float2*)(src + (size_t)row0 * KDIM + k0 + 8);
    const float2 p11 = *(const float2*)(src + (size_t)(row0 + 8) * KDIM + k0 + 8);
    uint4 h, l;
    split2(p00.x, p00.y, h.x, l.x);   // a0: (row g,   k..k+1)
    split2(p10.x, p10.y, h.y, l.y);   // a1: (row g+8, k..k+1)
    split2(p01.x, p01.y, h.z, l.z);   // a2: (row g,   k+8..k+9)
    split2(p11.x, p11.y, h.w, l.w);   // a3: (row g+8, k+8..k+9)
    d0[gid] = h;
    d1[gid] = l;
}

__global__ void __launch_bounds__(256)
pack_w16(const float* __restrict__ src, uint4* __restrict__ d0, uint4* __restrict__ d1)
{
    const uint32_t gid = blockIdx.x * 256 + threadIdx.x;
    const int lane = gid & 31;
    const int np   = (gid >> 5) & 7;
    const int k16  = (gid >> 8) & 1;
    const int kc   = (gid >> 9) & 15;
    const int nblk = gid >> 13;
    const int g = lane >> 2, tig = lane & 3;
    const int n0 = nblk * 128 + np * 16 + g;     // group u = np*2
    const int k0 = kc * 32 + k16 * 16 + tig * 2;
    const float2 q00 = *(const float2*)(src + (size_t)n0 * KDIM + k0);
    const float2 q01 = *(const float2*)(src + (size_t)n0 * KDIM + k0 + 8);
    const float2 q10 = *(const float2*)(src + (size_t)(n0 + 8) * KDIM + k0);
    const float2 q11 = *(const float2*)(src + (size_t)(n0 + 8) * KDIM + k0 + 8);
    uint4 h, l;
    split2(q00.x, q00.y, h.x, l.x);   // b0 of group u
    split2(q01.x, q01.y, h.y, l.y);   // b1 of group u
    split2(q10.x, q10.y, h.z, l.z);   // b0 of group u+1
    split2(q11.x, q11.y, h.w, l.w);   // b1 of group u+1
    d0[gid] = h;
    d1[gid] = l;
}

// ---- fused fp16x2-limb GEMM layer: act_clip(A @ W^T + bias) ----
// CTA 128x128 tile, BK=32, 3-stage cp.async pipeline (1 sync/chunk), 8 warps.
// launch_bounds(256, 2): cap regs at 128 so 2 CTAs co-reside per SM.
__global__ void __launch_bounds__(256, 2)
fused_layer16(const uint4* __restrict__ A0, const uint4* __restrict__ A1,
              const uint4* __restrict__ B0, const uint4* __restrict__ B1,
              const float* __restrict__ bias,
              const int*   __restrict__ fid,
              const float* __restrict__ mx,
              uint32_t* __restrict__ C0, uint32_t* __restrict__ C1,
              float* __restrict__ Cout,
              int Nout, int split_out)
{
    extern __shared__ __align__(16) uint32_t smw[];

    const int tid = threadIdx.x;
    const int w   = tid >> 5;
    const int l   = tid & 31;
    const int bn  = blockIdx.x * 128;
    const int wm  = w & 3;            // m block (rows wm*32)
    const int wn  = w >> 2;           // n half (cols wn*64)

    const uint32_t smem_addr = (uint32_t)__cvta_generic_to_shared(smw);
    const size_t a_base = (size_t)blockIdx.y * A_BLK_U4;
    const size_t b_base = (size_t)blockIdx.x * W_NBLK_U4;

    float acc[2][8][4];
    #pragma unroll
    for (int i = 0; i < 2; ++i)
        #pragma unroll
        for (int u = 0; u < 8; ++u)
            #pragma unroll
            for (int r = 0; r < 4; ++r) acc[i][u][r] = 0.0f;

    #define ISSUE_CHUNK(kc_) do {                                             \
        const uint32_t dstb = smem_addr + ((kc_) % NSTAGE) * (STAGE_WORDS*4); \
        const uint4* pA0 = A0 + a_base + (size_t)(kc_) * 512;                 \
        const uint4* pA1 = A1 + a_base + (size_t)(kc_) * 512;                 \
        const uint4* pB0 = B0 + b_base + (size_t)(kc_) * 512;                 \
        const uint4* pB1 = B1 + b_base + (size_t)(kc_) * 512;                 \
        _Pragma("unroll")                                                     \
        for (int j = 0; j < 2; ++j) {                                         \
            const int g16 = tid + j * 256;                                    \
            cp_async16(dstb +         g16 * 16, pA0 + g16);                   \
            cp_async16(dstb +  8192 + g16 * 16, pA1 + g16);                   \
            cp_async16(dstb + 16384 + g16 * 16, pB0 + g16);                   \
            cp_async16(dstb + 24576 + g16 * 16, pB1 + g16);                   \
        }                                                                     \
        asm volatile("cp.async.commit_group;" ::: "memory");                  \
    } while (0)

    // Prologue: 2 chunks in flight.
    ISSUE_CHUNK(0);
    ISSUE_CHUNK(1);

    constexpr int NCHUNK = KDIM / 32;   // 16
    for (int kc = 0; kc < NCHUNK; ++kc) {
        // chunk kc complete (<=1 newer group may still be pending)
        asm volatile("cp.async.wait_group 1;" ::: "memory");
        __syncthreads();

        // Refill the slot consumed at kc-1 (all reads ordered by the sync above).
        if (kc + 2 < NCHUNK) ISSUE_CHUNK(kc + 2);

        const uint32_t* sw = smw + (kc % NSTAGE) * STAGE_WORDS;
        #pragma unroll
        for (int k16 = 0; k16 < 2; ++k16) {
            const uint32_t* awb = sw + k16 * 1024;
            const uint4 ah0 = *(const uint4*)(awb + (wm * 2 + 0) * 128 + l * 4);
            const uint4 ah1 = *(const uint4*)(awb + (wm * 2 + 1) * 128 + l * 4);
            const uint4 al0 = *(const uint4*)(awb + 2048 + (wm * 2 + 0) * 128 + l * 4);
            const uint4 al1 = *(const uint4*)(awb + 2048 + (wm * 2 + 1) * 128 + l * 4);
            const uint32_t* bwb = sw + 4096 + k16 * 1024;
            #pragma unroll
            for (int pp = 0; pp < 4; ++pp) {
                const int np = wn * 4 + pp;
                const uint4 bh = *(const uint4*)(bwb + np * 128 + l * 4);
                const uint4 bl = *(const uint4*)(bwb + 2048 + np * 128 + l * 4);
                // group u = pp*2 (regs .x,.y), group u+1 (regs .z,.w)
                // acc += h0a*h0b + h0a*h1b + h1a*h0b
                mma16(acc[0][pp * 2],     ah0, bh.x, bh.y);
                mma16(acc[0][pp * 2],     ah0, bl.x, bl.y);
                mma16(acc[0][pp * 2],     al0, bh.x, bh.y);
                mma16(acc[1][pp * 2],     ah1, bh.x, bh.y);
                mma16(acc[1][pp * 2],     ah1, bl.x, bl.y);
                mma16(acc[1][pp * 2],     al1, bh.x, bh.y);
                mma16(acc[0][pp * 2 + 1], ah0, bh.z, bh.w);
                mma16(acc[0][pp * 2 + 1], ah0, bl.z, bl.w);
                mma16(acc[0][pp * 2 + 1], al0, bh.z, bh.w);
                mma16(acc[1][pp * 2 + 1], ah1, bh.z, bh.w);
                mma16(acc[1][pp * 2 + 1], ah1, bl.z, bl.w);
                mma16(acc[1][pp * 2 + 1], al1, bh.z, bh.w);
            }
        }
    }

    // ---- epilogue ----
    const int g = l >> 2;
    #pragma unroll
    for (int u = 0; u < 8; ++u) {
        const int col = bn + wn * 64 + u * 8 + (l & 3) * 2;
        const float bv0 = __ldg(bias + col);
        const float bv1 = __ldg(bias + col + 1);
        const int   f0  = __ldg(fid + col);
        const int   f1  = __ldg(fid + col + 1);
        const float m0  = __ldg(mx + col);
        const float m1  = __ldg(mx + col + 1);
        #pragma unroll
        for (int i = 0; i < 2; ++i) {
            const float* a4 = acc[i][u];
            const float v00 = act_clip(a4[0] + bv0, f0, m0);  // (row g,   col)
            const float v01 = act_clip(a4[1] + bv1, f1, m1);  // (row g,   col+1)
            const float v10 = act_clip(a4[2] + bv0, f0, m0);  // (row g+8, col)
            const float v11 = act_clip(a4[3] + bv1, f1, m1);  // (row g+8, col+1)
            if (split_out) {
                // packed fp16-limb write for next layer's A
                const int kc_  = col >> 5;
                const int k16_ = (col >> 4) & 1;
                const int kb   = (col >> 3) & 1;
                const int mt_  = wm * 2 + i;
                const size_t wb =
                    ((((size_t)blockIdx.y * 16 + kc_) * 2 + k16_) * 8 + mt_) * 128
                    + (size_t)l * 4;
                uint32_t w0h, w0l, w1h, w1l;
                split2(v00, v01, w0h, w0l);
                split2(v10, v11, w1h, w1l);
                C0[wb + 2 * kb]     = w0h;  C1[wb + 2 * kb]     = w0l;
                C0[wb + 1 + 2 * kb] = w1h;  C1[wb + 1 + 2 * kb] = w1l;
            } else {
                const int row0 = blockIdx.y * 128 + wm * 32 + i * 16 + g;
                *(float2*)(Cout + (size_t)row0 * Nout + col)       = make_float2(v00, v01);
                *(float2*)(Cout + (size_t)(row0 + 8) * Nout + col) = make_float2(v10, v11);
            }
        }
    }
}

extern "C" void kernel_launch(void* const* d_in, const int* in_sizes, int n_in,
                              void* d_out, int out_size) {
    const float* x      = (const float*)d_in[0];   // [65536, 512]
    const float* W_in   = (const float*)d_in[1];   // [512, 512]
    const float* b_in   = (const float*)d_in[2];   // [512]
    const float* W_h    = (const float*)d_in[3];   // [4, 512, 512]
    const float* b_h    = (const float*)d_in[4];   // [4, 512]
    const float* W_out  = (const float*)d_in[5];   // [128, 512]
    const float* b_out  = (const float*)d_in[6];   // [128]
    const float* m_in   = (const float*)d_in[7];   // [512]
    const float* m_h    = (const float*)d_in[8];   // [4, 512]
    const float* m_out  = (const float*)d_in[9];   // [128]
    const int*   fid_in = (const int*)d_in[10];    // [512]
    const int*   fid_h  = (const int*)d_in[11];    // [4, 512]
    const int*   fid_out= (const int*)d_in[12];    // [128]
    float* out = (float*)d_out;                    // [65536, 128]

    uint4 *A0a, *A1a, *A0b, *A1b, *W0, *W1;
    cudaGetSymbolAddress((void**)&A0a, g_A0a);
    cudaGetSymbolAddress((void**)&A1a, g_A1a);
    cudaGetSymbolAddress((void**)&A0b, g_A0b);
    cudaGetSymbolAddress((void**)&A1b, g_A1b);
    cudaGetSymbolAddress((void**)&W0, g_W0);
    cudaGetSymbolAddress((void**)&W1, g_W1);

    cudaFuncSetAttribute(fused_layer16,
                         cudaFuncAttributeMaxDynamicSharedMemorySize, SMEM_BYTES);

    // ---- one-time packing into fp16 limb fragment layout ----
    pack_a16<<<16384, 256>>>(x, A0a, A1a);
    pack_w16<<<128, 256>>>(W_in,  W0,                W1);                   // 4 n_blks
    pack_w16<<<512, 256>>>(W_h,   W0 + 4 * W_NBLK_U4,  W1 + 4 * W_NBLK_U4); // 16 n_blks
    pack_w16<<<32, 256>>>(W_out,  W0 + 20 * W_NBLK_U4, W1 + 20 * W_NBLK_U4);// 1 n_blk

    dim3 blk(256);
    dim3 g512(4, B_TOTAL / 128);
    dim3 g128(1, B_TOTAL / 128);

    // input layer: packed A(a) -> packed A(b)
    fused_layer16<<<g512, blk, SMEM_BYTES>>>(A0a, A1a, W0, W1,
                                             b_in, fid_in, m_in,
                                             (uint32_t*)A0b, (uint32_t*)A1b,
                                             nullptr, 512, 1);

    // 4 hidden layers, ping-pong
    const uint4* c0 = A0b; const uint4* c1 = A1b;
    uint4* n0 = A0a;       uint4* n1 = A1a;
    for (int i = 0; i < 4; ++i) {
        const size_t woff = (size_t)(4 + 4 * i) * W_NBLK_U4;
        fused_layer16<<<g512, blk, SMEM_BYTES>>>(c0, c1, W0 + woff, W1 + woff,
                                                 b_h + i * 512,
                                                 fid_h + i * 512,
                                                 m_h + i * 512,
                                                 (uint32_t*)n0, (uint32_t*)n1,
                                                 nullptr, 512, 1);
        uint4* t0 = n0; uint4* t1 = n1;
        n0 = (uint4*)c0; n1 = (uint4*)c1;
        c0 = t0; c1 = t1;
    }

    // output layer: plain fp32 row-major out
    fused_layer16<<<g128, blk, SMEM_BYTES>>>(c0, c1,
                                             W0 + 20 * W_NBLK_U4, W1 + 20 * W_NBLK_U4,
                                             b_out, fid_out, m_out,
                                             nullptr, nullptr, out, 128, 0);
}